// round 14
// baseline (speedup 1.0000x reference)
#include <cuda_runtime.h>
#include <cuda_fp16.h>
#include <cstdint>

// MaddnessConv2d, round 14: 1 lane/pixel, fp16 LUT, 8-slot rotation
// (conflict-free LDS for any code), uniform-offset coalesced gathers,
// no shuffles, pair-add fp16 accumulation, pad-9 transpose overlay.
//
//   x:            (16, 64, 56, 56) f32
//   split_idxs:   (16, 4) i32
//   split_vals:   (16, 4, 8) f32
//   lookup_tables:(16, 16, 64) f32
//   bias:         (64,) f32
//   out:          (16, 64, 56, 56) f32
//
// out[p][ch] = sum_cb LUT[cb][e_cb(p)][ch] + bias[ch]. LUT in smem as fp16
// (row (cb,e) = 128B = 8 slots x 8 channels). Thread owns a whole pixel:
// slot visitation s = (j + lane)&7 -> every 8-lane LDS phase covers all 8
// banks regardless of e. acc[j] holds channel-group g=(j+lane)&7; un-rotated
// via pad-9 smem transpose in the dead LUT region; fp32 finalize + bias at
// fully-coalesced stores. Gathers: offset uniform per warp-op -> 128B lines.

#define NCB   16
#define HW    3136          // 56*56
#define WID   56
#define TPB   128
#define NBLK  392           // 392*128 == 50176: 1 thread = 1 pixel

__global__ __launch_bounds__(TPB, 6) void maddness_conv2d_kernel(
    const float* __restrict__ x,
    const int*   __restrict__ split_idxs,
    const float* __restrict__ split_vals,
    const float* __restrict__ lut,
    const float* __restrict__ bias,
    float*       __restrict__ out)
{
    __shared__ uint4  s_lut[2048];        // 32KB fp16 LUT; overlaid by s_buf
    __shared__ float  s_bias[64];
    __shared__ float  s_sval[16 * 33];    // stride-33 (broadcast-friendly walk)
    __shared__ int    s_off[64];
    __shared__ int    s_kpos[64];

    const int tid = threadIdx.x;

    // --- per-block setup: convert LUT fp32 -> fp16 (128B rows) ---
    {
        const float4* lut4 = (const float4*)lut;   // 4096 float4 (4 ch each)
        char* s_lutb = (char*)s_lut;
        #pragma unroll
        for (int i = tid; i < 4096; i += TPB) {
            float4 lv = lut4[i];
            __half2 h0 = __floats2half2_rn(lv.x, lv.y);
            __half2 h1 = __floats2half2_rn(lv.z, lv.w);
            uint2 pk;
            pk.x = *(unsigned*)&h0;
            pk.y = *(unsigned*)&h1;
            *(uint2*)(s_lutb + (i >> 4) * 128 + (i & 15) * 8) = pk;
        }
    }
    if (tid < 64) {
        int cb = tid >> 2;                 // tid = cb*4 + t
        int si = split_idxs[tid];
        int f  = cb * 36 + si;
        int ch = f / 9;
        int r  = f - ch * 9;               // kernel position 0..8
        int dy = r / 3 - 1;
        int dx = r - (r / 3) * 3 - 1;
        s_off[tid]  = ch * HW + dy * WID + dx;
        s_kpos[tid] = r;
        s_bias[tid] = bias[tid];
    }
    #pragma unroll
    for (int i = tid; i < NCB * 32; i += TPB)
        s_sval[(i >> 5) * 33 + (i & 31)] = split_vals[i];
    __syncthreads();

    // --- my pixel ---
    const int p   = blockIdx.x * TPB + tid;    // exact grid
    const int b   = p / HW;
    const int rem = p - b * HW;
    const int y   = rem / WID;
    const int xw  = rem - y * WID;
    const float* xb = x + (size_t)b * 64 * HW + rem;

    // 3x3 validity bitmask (pad=1)
    unsigned vm = 0;
    #pragma unroll
    for (int ki = 0; ki < 3; ki++)
        #pragma unroll
        for (int kj = 0; kj < 3; kj++) {
            bool ok = ((unsigned)(y + ki - 1) < 56u) & ((unsigned)(xw + kj - 1) < 56u);
            vm |= (ok ? 1u : 0u) << (ki * 3 + kj);
        }

    // --- encode all 16 codebooks; gathers are warp-uniform offsets,
    //     batched 16 at a time (4 codebooks) for MLP ---
    unsigned long long codes = 0ull;
    #pragma unroll
    for (int batch = 0; batch < 4; batch++) {
        float v[16];
        #pragma unroll
        for (int q = 0; q < 16; q++) {
            const int idx = batch * 16 + q;    // (cb = idx>>2, t = idx&3)
            v[q] = ((vm >> s_kpos[idx]) & 1u) ? __ldg(xb + s_off[idx]) : 0.0f;
        }
        #pragma unroll
        for (int c = 0; c < 4; c++) {
            const int cb = batch * 4 + c;
            int e = 0;
            #pragma unroll
            for (int t = 0; t < 4; t++) {
                const float thr = s_sval[cb * 33 + t * 8 + e];
                e = 2 * e + (v[c * 4 + t] >= thr ? 1 : 0);
            }
            codes |= (unsigned long long)e << (4 * cb);
        }
    }

    // --- accumulate: acc[j] = channel-group g=(j+rot)&7; pair-add trees ---
    const int rot = tid & 7;
    __half2 acc[8][4];
    #pragma unroll
    for (int j = 0; j < 8; j++)
        #pragma unroll
        for (int k = 0; k < 4; k++) acc[j][k] = __half2half2(__ushort_as_half(0));

    #pragma unroll
    for (int cbp = 0; cbp < 8; cbp++) {
        const int eA = (int)((codes >> (8 * cbp)) & 15ull);
        const int eB = (int)((codes >> (8 * cbp + 4)) & 15ull);
        const uint4* rowA = s_lut + ((2 * cbp)     * 16 + eA) * 8;
        const uint4* rowB = s_lut + ((2 * cbp + 1) * 16 + eB) * 8;
        #pragma unroll
        for (int j = 0; j < 8; j++) {
            const int s = (j + rot) & 7;
            uint4 a = rowA[s];
            uint4 bq = rowB[s];
            __half2 t0 = __hadd2(*(__half2*)&a.x, *(__half2*)&bq.x);
            __half2 t1 = __hadd2(*(__half2*)&a.y, *(__half2*)&bq.y);
            __half2 t2 = __hadd2(*(__half2*)&a.z, *(__half2*)&bq.z);
            __half2 t3 = __hadd2(*(__half2*)&a.w, *(__half2*)&bq.w);
            acc[j][0] = __hadd2(acc[j][0], t0);
            acc[j][1] = __hadd2(acc[j][1], t1);
            acc[j][2] = __hadd2(acc[j][2], t2);
            acc[j][3] = __hadd2(acc[j][3], t3);
        }
    }

    // --- un-rotate via pad-9 transpose in the dead LUT region ---
    __syncthreads();                           // all LUT reads complete
    uint4* s_buf = s_lut;                      // [px:128][g:8] at px*9 + g
    #pragma unroll
    for (int j = 0; j < 8; j++) {
        const int g = (j + rot) & 7;
        uint4 pk;
        pk.x = *(unsigned*)&acc[j][0];
        pk.y = *(unsigned*)&acc[j][1];
        pk.z = *(unsigned*)&acc[j][2];
        pk.w = *(unsigned*)&acc[j][3];
        s_buf[tid * 9 + g] = pk;
    }
    __syncthreads();

    // --- coalesced stores with fp32 finalize + bias (thread = its pixel) ---
    float* ob = out + (size_t)b * 64 * HW + rem;
    #pragma unroll
    for (int g = 0; g < 8; g++) {
        uint4 pk = s_buf[tid * 9 + g];         // conflict-free (pad 9)
        float2 f0 = __half22float2(*(__half2*)&pk.x);
        float2 f1 = __half22float2(*(__half2*)&pk.y);
        float2 f2 = __half22float2(*(__half2*)&pk.z);
        float2 f3 = __half22float2(*(__half2*)&pk.w);
        const int ch = 8 * g;
        ob[(ch + 0) * HW] = f0.x + s_bias[ch + 0];
        ob[(ch + 1) * HW] = f0.y + s_bias[ch + 1];
        ob[(ch + 2) * HW] = f1.x + s_bias[ch + 2];
        ob[(ch + 3) * HW] = f1.y + s_bias[ch + 3];
        ob[(ch + 4) * HW] = f2.x + s_bias[ch + 4];
        ob[(ch + 5) * HW] = f2.y + s_bias[ch + 5];
        ob[(ch + 6) * HW] = f3.x + s_bias[ch + 6];
        ob[(ch + 7) * HW] = f3.y + s_bias[ch + 7];
    }
}

extern "C" void kernel_launch(void* const* d_in, const int* in_sizes, int n_in,
                              void* d_out, int out_size)
{
    const float* x    = (const float*)d_in[0];
    const int*   sidx = (const int*)  d_in[1];
    const float* sval = (const float*)d_in[2];
    const float* lut  = (const float*)d_in[3];
    const float* bias = (const float*)d_in[4];
    float* out = (float*)d_out;

    maddness_conv2d_kernel<<<NBLK, TPB>>>(x, sidx, sval, lut, bias, out);
}